// round 6
// baseline (speedup 1.0000x reference)
#include <cuda_runtime.h>

#define NB 16
#define NA 3
#define NM 32
#define NC 80
#define NH 80
#define NW 80
#define NHW (NH * NW)                 // 6400
#define CH (NA * (5 + NC) + NA * NM)  // 351
#define NE (NB * NA * NHW)            // 307200
#define TPB 256
#define NBLK (NE / TPB)               // 1200
#define THRESH 0.05f
#define STRIDEF 8.0f
#define ROW (7 + NM)                  // 39

#define FLAG_AGG  (1ull << 62)
#define FLAG_PRE  (2ull << 62)

__device__ unsigned long long g_state[NBLK];

__global__ void init_kernel()
{
    int i = blockIdx.x * blockDim.x + threadIdx.x;
    if (i < NBLK) g_state[i] = 0ull;
}

__global__ void __launch_bounds__(TPB, 6)
fused_kernel(const float* __restrict__ in, const float* __restrict__ anchors,
             float* __restrict__ out, long long out_size)
{
    const int tid  = threadIdx.x;
    const int lane = tid & 31;
    const int wid  = tid >> 5;
    const int bid  = blockIdx.x;

    const int e = bid * TPB + tid;
    const int b = e / (NA * NHW);
    const int r = e - b * (NA * NHW);
    const int a = r / NHW;
    const int p = r - a * NHW;

    const float* base = in + ((size_t)b * CH + (size_t)a * (5 + NC)) * NHW + p;

    // ---- max-free softmax over NC logits: cls_max = exp(m)/sum(exp(x)) ----
    float m = -1e30f, s = 0.0f;
    int idx = 0;
    const float* cb = base + 5 * NHW;
#pragma unroll 10
    for (int c = 0; c < NC; ++c) {
        float x = __ldg(cb + c * NHW);
        s += __expf(x);
        if (x > m) { m = x; idx = c; }
    }

    const float obj = 1.0f / (1.0f + expf(-__ldg(base + 4 * NHW)));  // accurate
    const float score = obj * __expf(m) / s;
    const bool keep = score > THRESH;

    // ---- block rank ----
    __shared__ int s_warp[TPB / 32];
    __shared__ int s_cut;
    __shared__ int s_red[TPB / 32];
    const unsigned ball = __ballot_sync(0xffffffffu, keep);
    if (lane == 0) s_warp[wid] = __popc(ball);
    __syncthreads();

    // every thread computes warp-prefix + total from smem (8 ints)
    int texcl = 0, total = 0;
#pragma unroll
    for (int i = 0; i < TPB / 32; ++i) {
        int c = s_warp[i];
        if (i < wid) texcl += c;
        total += c;
    }
    texcl += __popc(ball & ((1u << lane) - 1u));

    // publish this block's aggregate immediately
    if (tid == 0) {
        unsigned long long v = (bid == 0 ? FLAG_PRE : FLAG_AGG) | (unsigned)total;
        atomicExch(&g_state[bid], v);
    }

    // ---- block-wide decoupled lookback: 256 predecessors per step ----
    int excl = 0;
    if (bid != 0) {
        int j = bid - 1;
        for (;;) {
            const int gidx = j - tid;
            unsigned long long v;
            if (gidx >= 0) {
                do {
                    v = *(volatile const unsigned long long*)&g_state[gidx];
                } while ((v >> 62) == 0ull);
            } else {
                v = FLAG_PRE;  // count 0: terminates the search
            }
            const bool isPre = (v >> 62) == 2ull;

            if (tid == 0) s_cut = TPB;
            __syncthreads();
            const unsigned pb = __ballot_sync(0xffffffffu, isPre);
            if (pb && lane == (__ffs(pb) - 1)) atomicMin_block(&s_cut, tid);
            __syncthreads();
            const int cut = s_cut;

            const unsigned add = (tid <= cut) ? (unsigned)(v & 0xffffffffu) : 0u;
            const unsigned wsum = __reduce_add_sync(0xffffffffu, add);
            if (lane == 0) s_red[wid] = wsum;
            __syncthreads();
            int step = 0;
#pragma unroll
            for (int i = 0; i < TPB / 32; ++i) step += s_red[i];
            excl += step;

            if (cut < TPB) break;
            j -= TPB;
            __syncthreads();   // before s_cut / s_red reuse
        }
        if (tid == 0)
            atomicExch(&g_state[bid], FLAG_PRE | (unsigned)(excl + total));
    }

    if (total == 0) return;

    const int row = excl + texcl;
    const long long o = (long long)row * ROW;
    const bool wok = keep && (o + ROW <= out_size);

    if (wok) {
        const float x0 = __ldg(base + 0 * NHW);
        const float y0 = __ldg(base + 1 * NHW);
        const float w0 = __ldg(base + 2 * NHW);
        const float h0 = __ldg(base + 3 * NHW);

        const float aw = anchors[a * 2 + 0];
        const float ah = anchors[a * 2 + 1];
        const float amax = fmaxf(fmaxf(fmaxf(anchors[0], anchors[1]),
                                       fmaxf(anchors[2], anchors[3])),
                                 fmaxf(anchors[4], anchors[5]));
        const float maxv = floorf(logf(1e35f / amax / STRIDEF));

        const float xs = (1.0f / (1.0f + __expf(-x0)) + (float)(p % NW)) * STRIDEF;
        const float ys = (1.0f / (1.0f + __expf(-y0)) + (float)(p / NW)) * STRIDEF;
        const float wv = __expf(fminf(w0, maxv)) * aw * STRIDEF;
        const float hv = __expf(fminf(h0, maxv)) * ah * STRIDEF;

        out[o + 0] = (float)b;
        out[o + 1] = xs;
        out[o + 2] = ys;
        out[o + 3] = wv;
        out[o + 4] = hv;
        out[o + 5 + NM] = score;
        out[o + 6 + NM] = (float)idx;

        const float* mb = in + ((size_t)b * CH + NA * (5 + NC) + (size_t)a * NM) * NHW + p;
#pragma unroll 8
        for (int mi = 0; mi < NM; ++mi)
            out[o + 5 + mi] = __ldg(mb + mi * NHW);
    }
}

extern "C" void kernel_launch(void* const* d_in, const int* in_sizes, int n_in,
                              void* d_out, int out_size)
{
    const float* in      = (const float*)d_in[0];
    const float* anchors = (const float*)d_in[1];
    float* out = (float*)d_out;

    init_kernel<<<(NBLK + 255) / 256, 256>>>();
    fused_kernel<<<NBLK, TPB>>>(in, anchors, out, (long long)out_size);
}

// round 7
// speedup vs baseline: 1.1070x; 1.1070x over previous
#include <cuda_runtime.h>

#define NB 16
#define NA 3
#define NM 32
#define NC 80
#define NH 80
#define NW 80
#define NHW (NH * NW)                 // 6400
#define CH (NA * (5 + NC) + NA * NM)  // 351
#define NE (NB * NA * NHW)            // 307200
#define TPB 256
#define NBLK (NE / TPB)               // 1200
#define THRESH 0.05f
#define STRIDEF 8.0f
#define ROW (7 + NM)                  // 39

// state word: bits[63:62] flag (0=invalid, 1=AGG, 2=PRE), bit[61] round parity,
// bits[31:0] count. Stale entries from the previous launch carry the opposite
// parity and therefore read as not-ready; no reset kernel needed.
__device__ unsigned long long g_state[NBLK];   // zero-init at module load
__device__ int g_round = 0;

__global__ void __launch_bounds__(TPB, 6)
fused_kernel(const float* __restrict__ in, const float* __restrict__ anchors,
             float* __restrict__ out, long long out_size)
{
    const int tid  = threadIdx.x;
    const int lane = tid & 31;
    const int wid  = tid >> 5;
    const int bid  = blockIdx.x;

    const unsigned round = (unsigned)*(volatile const int*)&g_round;

    const int e = bid * TPB + tid;
    const int b = e / (NA * NHW);
    const int r = e - b * (NA * NHW);
    const int a = r / NHW;
    const int p = r - a * NHW;

    const float* base = in + ((size_t)b * CH + (size_t)a * (5 + NC)) * NHW + p;

    // ---- max-free softmax over NC logits: cls_max = exp(m)/sum(exp(x)) ----
    float m = -1e30f, s = 0.0f;
    int idx = 0;
    const float* cb = base + 5 * NHW;
#pragma unroll 10
    for (int c = 0; c < NC; ++c) {
        float x = __ldg(cb + c * NHW);
        s += __expf(x);
        if (x > m) { m = x; idx = c; }
    }

    const float obj = 1.0f / (1.0f + expf(-__ldg(base + 4 * NHW)));  // accurate
    const float score = obj * __expf(m) / s;
    const bool keep = score > THRESH;

    // ---- block-wide ordered rank ----
    __shared__ int s_warp[TPB / 32];
    __shared__ int s_base;
    const unsigned ball = __ballot_sync(0xffffffffu, keep);
    if (lane == 0) s_warp[wid] = __popc(ball);
    __syncthreads();
    if (wid == 0 && lane < TPB / 32) {
        int w = s_warp[lane];
#pragma unroll
        for (int d = 1; d < TPB / 32; d <<= 1) {
            int n = __shfl_up_sync(0xffu, w, d);
            if (lane >= d) w += n;
        }
        s_warp[lane] = w;   // inclusive prefix over warps
    }
    __syncthreads();
    const int total = s_warp[TPB / 32 - 1];
    const int texcl = (wid ? s_warp[wid - 1] : 0) + __popc(ball & ((1u << lane) - 1u));

    const unsigned long long RB   = (unsigned long long)round << 61;
    const unsigned long long AGGT = (1ull << 62) | RB;
    const unsigned long long PRET = (2ull << 62) | RB;

    // ---- decoupled lookback (warp 0), round-tagged ----
    if (wid == 0) {
        if (bid == 0) {
            if (lane == 0) {
                atomicExch(&g_state[0], PRET | (unsigned)total);
                s_base = 0;
            }
        } else {
            if (lane == 0)
                atomicExch(&g_state[bid], AGGT | (unsigned)total);
            int excl = 0;
            int j = bid - 1;
            while (j >= 0) {
                const int gidx = j - lane;
                const bool valid = gidx >= 0;
                unsigned long long v;
                bool ready;
                bool first = true;
                do {
                    if (!first) __nanosleep(40);
                    first = false;
                    v = valid ? *(volatile const unsigned long long*)&g_state[gidx]
                              : PRET;
                    ready = ((v >> 62) != 0ull) &&
                            ((unsigned)((v >> 61) & 1ull) == round);
                } while (__any_sync(0xffffffffu, !ready));
                const unsigned pmask = __ballot_sync(0xffffffffu, (v >> 62) == 2ull);
                const int cut = pmask ? (__ffs(pmask) - 1) : 32;
                const unsigned add = (lane <= (cut < 31 ? cut : 31)) ? (unsigned)(v & 0xffffffffu) : 0u;
                excl += (int)__reduce_add_sync(0xffffffffu, add);
                if (cut < 32) break;
                j -= 32;
            }
            if (lane == 0) {
                atomicExch(&g_state[bid], PRET | (unsigned)(excl + total));
                s_base = excl;
            }
        }
        // Last block's lookback completing proves every block has already
        // started (and thus read g_round) -> safe to flip for the next launch.
        if (bid == NBLK - 1 && lane == 0)
            *(volatile int*)&g_round = (int)(round ^ 1u);
    }
    __syncthreads();

    if (total == 0) return;

    const int row = s_base + texcl;
    const long long o = (long long)row * ROW;
    const bool wok = keep && (o + ROW <= out_size);

    if (wok) {
        const float x0 = __ldg(base + 0 * NHW);
        const float y0 = __ldg(base + 1 * NHW);
        const float w0 = __ldg(base + 2 * NHW);
        const float h0 = __ldg(base + 3 * NHW);

        const float aw = anchors[a * 2 + 0];
        const float ah = anchors[a * 2 + 1];
        const float amax = fmaxf(fmaxf(fmaxf(anchors[0], anchors[1]),
                                       fmaxf(anchors[2], anchors[3])),
                                 fmaxf(anchors[4], anchors[5]));
        const float maxv = floorf(logf(1e35f / amax / STRIDEF));

        const float xs = (1.0f / (1.0f + __expf(-x0)) + (float)(p % NW)) * STRIDEF;
        const float ys = (1.0f / (1.0f + __expf(-y0)) + (float)(p / NW)) * STRIDEF;
        const float wv = __expf(fminf(w0, maxv)) * aw * STRIDEF;
        const float hv = __expf(fminf(h0, maxv)) * ah * STRIDEF;

        out[o + 0] = (float)b;
        out[o + 1] = xs;
        out[o + 2] = ys;
        out[o + 3] = wv;
        out[o + 4] = hv;
        out[o + 5 + NM] = score;
        out[o + 6 + NM] = (float)idx;

        const float* mb = in + ((size_t)b * CH + NA * (5 + NC) + (size_t)a * NM) * NHW + p;
#pragma unroll 8
        for (int mi = 0; mi < NM; ++mi)
            out[o + 5 + mi] = __ldg(mb + mi * NHW);
    }
}

extern "C" void kernel_launch(void* const* d_in, const int* in_sizes, int n_in,
                              void* d_out, int out_size)
{
    const float* in      = (const float*)d_in[0];
    const float* anchors = (const float*)d_in[1];
    float* out = (float*)d_out;

    fused_kernel<<<NBLK, TPB>>>(in, anchors, out, (long long)out_size);
}